// round 16
// baseline (speedup 1.0000x reference)
#include <cuda_runtime.h>
#include <math.h>

#define H 128
#define W 128
#define HW 16384
#define BATCH 4
#define NF 64
#define TOPK 3

typedef unsigned long long ull;

__device__ __forceinline__ ull pk2(float a, float b) {
    ull r; asm("mov.b64 %0,{%1,%2};" : "=l"(r) : "f"(a), "f"(b)); return r;
}
__device__ __forceinline__ void upk2(ull v, float& a, float& b) {
    asm("mov.b64 {%0,%1},%2;" : "=f"(a), "=f"(b) : "l"(v));
}
__device__ __forceinline__ void ffma2(ull& d, ull a, ull b) {
    asm("fma.rn.f32x2 %0,%1,%2,%0;" : "+l"(d) : "l"(a), "l"(b));
}
__device__ __forceinline__ unsigned smaddr(const void* p) {
    return (unsigned)__cvta_generic_to_shared(p);
}
__device__ __forceinline__ void cp4(unsigned s, const void* g, int pred) {
    asm volatile("{\n\t.reg .pred p;\n\tsetp.ne.u32 p,%2,0;\n\t"
                 "@p cp.async.ca.shared.global [%0],[%1],4;\n\t}"
                 :: "r"(s), "l"(g), "r"(pred));
}
__device__ __forceinline__ void cp16(unsigned s, const void* g, int pred) {
    asm volatile("{\n\t.reg .pred p;\n\tsetp.ne.u32 p,%2,0;\n\t"
                 "@p cp.async.cg.shared.global [%0],[%1],16;\n\t}"
                 :: "r"(s), "l"(g), "r"(pred));
}
__device__ __forceinline__ void cp_commit() { asm volatile("cp.async.commit_group;"); }
template<int N> __device__ __forceinline__ void cp_wait() {
    asm volatile("cp.async.wait_group %0;" :: "n"(N));
}

__device__ __forceinline__ unsigned bf16pack(float v0, float v1) {
    unsigned r;
    asm("cvt.rn.satfinite.bf16x2.f32 %0,%1,%2;" : "=r"(r) : "f"(v1), "f"(v0));
    return r;
}
__device__ __forceinline__ void packHL(float v0, float v1, unsigned& hi, unsigned& lo) {
    hi = bf16pack(v0, v1);
    float l0 = v0 - __uint_as_float(hi << 16);
    float l1 = v1 - __uint_as_float(hi & 0xffff0000u);
    lo = bf16pack(l0, l1);
}

__device__ __forceinline__ void mma_bf16(float* d, const unsigned* a, unsigned b0, unsigned b1) {
    asm("mma.sync.aligned.m16n8k16.row.col.f32.bf16.bf16.f32 "
        "{%0,%1,%2,%3}, {%4,%5,%6,%7}, {%8,%9}, {%0,%1,%2,%3};"
        : "+f"(d[0]), "+f"(d[1]), "+f"(d[2]), "+f"(d[3])
        : "r"(a[0]), "r"(a[1]), "r"(a[2]), "r"(a[3]), "r"(b0), "r"(b1));
}
__device__ __forceinline__ void ldsm4(unsigned* r, unsigned addr) {
    asm volatile("ldmatrix.sync.aligned.m8n8.x4.shared.b16 {%0,%1,%2,%3}, [%4];"
                 : "=r"(r[0]), "=r"(r[1]), "=r"(r[2]), "=r"(r[3]) : "r"(addr));
}

// ---------------- device global scratch --------------------------------------
static __device__ float g_sup [TOPK*BATCH*HW];
static __device__ float g_ref [TOPK*BATCH*NF*HW];
static __device__ float g_off [TOPK*BATCH*18*HW];
static __device__ float g_mod [TOPK*BATCH*9*HW];
static __device__ float g_xA  [BATCH*NF*HW];
static __device__ float g_wom [TOPK*128*9*32];
static __device__ float g_wreg[TOPK*64*9*64];
static __device__ unsigned g_wbm1[8*36864];   // PLAIN: [conv][tap][part][oc][32 p]
static __device__ unsigned g_wbm2[8*36864];
static __device__ unsigned g_wfb [73728];     // PLAIN: [18 it][part][oc][32 p]
static __device__ unsigned g_pXhi[BATCH*HW*32];
static __device__ unsigned g_pXlo[BATCH*HW*32];
static __device__ unsigned g_pThi[BATCH*HW*32];
static __device__ unsigned g_pTlo[BATCH*HW*32];
static __device__ unsigned g_pUhi[BATCH*HW*32];
static __device__ unsigned g_pUlo[BATCH*HW*32];
static __device__ unsigned g_pVhi[BATCH*HW*32];
static __device__ unsigned g_pVlo[BATCH*HW*32];

// ---------------- weight transposes ------------------------------------------
__global__ void wt_generic(const float* __restrict__ src, float* __restrict__ dst,
                           int O, int C, int OP, int total) {
    int idx = blockIdx.x * blockDim.x + threadIdx.x;
    if (idx >= total) return;
    int per = C * 9 * OP;
    int s = idx / per;
    int r = idx - s * per;
    int c = r / (9 * OP);
    int r2 = r - c * (9 * OP);
    int k = r2 / OP;
    int o = r2 - k * OP;
    dst[idx] = (o < O) ? src[((s * O + o) * C + c) * 9 + k] : 0.f;
}

__global__ void wt_om(const float* __restrict__ offw, const float* __restrict__ modw) {
    int idx = blockIdx.x * blockDim.x + threadIdx.x;
    const int total = TOPK * 128 * 9 * 32;
    if (idx >= total) return;
    int i = idx / (128 * 9 * 32);
    int r = idx - i * (128 * 9 * 32);
    int c = r / (9 * 32);
    int r2 = r - c * (9 * 32);
    int k = r2 / 32;
    int o = r2 - k * 32;
    float v = 0.f;
    if (o < 18)      v = offw[((i * 18 + o) * 128 + c) * 9 + k];
    else if (o < 27) v = modw[((i * 9 + (o - 18)) * 128 + c) * 9 + k];
    g_wom[idx] = v;
}

// rb weights -> bf16 hi/lo PLAIN fragment layout
__global__ void wt_wbm(const float* __restrict__ src, unsigned* __restrict__ dst) {
    int idx = blockIdx.x * blockDim.x + threadIdx.x;
    const int total = 8 * 9 * 64 * 32;
    if (idx >= total) return;
    int conv = idx / 18432;
    int r = idx - conv * 18432;
    int tap = r / 2048;
    int r2 = r - tap * 2048;
    int oc = r2 >> 5;
    int p = r2 & 31;
    int c = 2 * p;
    float v0 = src[((conv * 64 + oc) * 64 + c) * 9 + tap];
    float v1 = src[((conv * 64 + oc) * 64 + c + 1) * 9 + tap];
    unsigned hi, lo;
    packHL(v0, v1, hi, lo);
    dst[(((conv * 9 + tap) * 2 + 0) * 64 + oc) * 32 + p] = hi;
    dst[(((conv * 9 + tap) * 2 + 1) * 64 + oc) * 32 + p] = lo;
}

// fuse weights -> PLAIN fragment layout, 18 (half,tap) images
__global__ void wt_wfb(const float* __restrict__ src) {
    int idx = blockIdx.x * blockDim.x + threadIdx.x;
    const int total = 2 * 9 * 64 * 32;
    if (idx >= total) return;
    int h = idx / 18432;
    int r = idx - h * 18432;
    int tap = r / 2048;
    int r2 = r - tap * 2048;
    int oc = r2 >> 5;
    int p = r2 & 31;
    int c = h * 64 + 2 * p;
    float v0 = src[(oc * 128 + c) * 9 + tap];
    float v1 = src[(oc * 128 + c + 1) * 9 + tap];
    unsigned hi, lo;
    packHL(v0, v1, hi, lo);
    g_wfb[(((h * 9 + tap) * 2 + 0) * 64 + oc) * 32 + p] = hi;
    g_wfb[(((h * 9 + tap) * 2 + 1) * 64 + oc) * 32 + p] = lo;
}

__global__ void pack_x(const float* __restrict__ x) {
    int idx = blockIdx.x * blockDim.x + threadIdx.x;
    const int total = BATCH * HW * 32;
    if (idx >= total) return;
    int b = idx / (HW * 32);
    int r = idx - b * (HW * 32);
    int px = r >> 5;
    int cp = r & 31;
    float v0 = x[(b * NF + 2 * cp) * HW + px];
    float v1 = x[(b * NF + 2 * cp + 1) * HW + px];
    unsigned hi, lo;
    packHL(v0, v1, hi, lo);
    g_pUhi[idx] = hi;
    g_pUlo[idx] = lo;
}

// ---------------- bicubic 2x upsample ----------------------------------------
__global__ void sup_kernel(const float* __restrict__ S) {
    int idx = blockIdx.x * blockDim.x + threadIdx.x;
    if (idx >= TOPK * BATCH * HW) return;
    int ib = idx / HW;
    int p = idx & (HW - 1);
    int oy = p >> 7, ox = p & 127;
    const float* s = S + ib * 64 * 64;
    const float wE0 = -0.03515625f, wE1 = 0.26171875f, wE2 = 0.87890625f, wE3 = -0.10546875f;
    float wy[4], wx[4];
    if (oy & 1) { wy[0] = wE3; wy[1] = wE2; wy[2] = wE1; wy[3] = wE0; }
    else        { wy[0] = wE0; wy[1] = wE1; wy[2] = wE2; wy[3] = wE3; }
    if (ox & 1) { wx[0] = wE3; wx[1] = wE2; wx[2] = wE1; wx[3] = wE0; }
    else        { wx[0] = wE0; wx[1] = wE1; wx[2] = wE2; wx[3] = wE3; }
    int iy0 = (int)floorf(0.5f * (float)oy - 0.25f) - 1;
    int ix0 = (int)floorf(0.5f * (float)ox - 0.25f) - 1;
    float acc = 0.f;
    #pragma unroll
    for (int jy = 0; jy < 4; ++jy) {
        int yy = min(max(iy0 + jy, 0), 63);
        float row = 0.f;
        #pragma unroll
        for (int jx = 0; jx < 4; ++jx) {
            int xx = min(max(ix0 + jx, 0), 63);
            row += wx[jx] * s[yy * 64 + xx];
        }
        acc += wy[jy] * row;
    }
    g_sup[idx] = acc;
}

// ---------------- ref = T * broadcast(S_up) ----------------------------------
__global__ void ref_kernel(const float* __restrict__ T) {
    int idx = blockIdx.x * blockDim.x + threadIdx.x;
    const int total = TOPK * BATCH * NF * HW / 4;
    if (idx >= total) return;
    int q = idx & 4095;
    int ibc = idx >> 12;
    int ib = ibc / NF;
    float4 t = ((const float4*)T)[idx];
    float4 s = ((const float4*)g_sup)[ib * 4096 + q];
    float4 r;
    r.x = t.x * s.x; r.y = t.y * s.y; r.z = t.z * s.z; r.w = t.w * s.w;
    ((float4*)g_ref)[idx] = r;
}

// ---------------- offset/modulator conv (pipelined FFMA2) --------------------
__global__ void __launch_bounds__(256) convom_kernel(const float* __restrict__ x,
                                                     const float* __restrict__ off_b,
                                                     const float* __restrict__ mod_b) {
    __shared__ float patchB[2][1632];
    __shared__ __align__(16) float wsmB[2][2304];
    int tid = threadIdx.x;
    int bx = blockIdx.x, by = blockIdx.y, z = blockIdx.z;
    int i = z >> 2, b = z & 3;
    const float* inA = x + b * NF * HW;
    const float* inB = g_ref + (i * BATCH + b) * NF * HW;
    const float* wT = g_wom + i * (128 * 9 * 32);
    int g = tid >> 5, col = tid & 31;
    ull acc[4][2];
    #pragma unroll
    for (int a = 0; a < 4; ++a) { acc[a][0] = 0ull; acc[a][1] = 0ull; }

    int fgo[7], fso[7], fcp[7]; int fva[7];
    #pragma unroll
    for (int f = 0; f < 7; ++f) {
        int idx = tid + f * 256;
        int c = idx / 204;
        int rr = idx - c * 204;
        int r = rr / 34;
        int cl = rr - r * 34;
        int y = by * 4 + r - 1, xx = bx * 32 + cl - 1;
        fcp[f] = (c & 7) * HW;
        fgo[f] = y * 128 + xx;
        fso[f] = idx;
        fva[f] = (idx < 1632) && ((unsigned)y < 128u) && ((unsigned)xx < 128u);
    }

    for (int idx = tid; idx < 1632; idx += 256) { patchB[0][idx] = 0.f; patchB[1][idx] = 0.f; }
    __syncthreads();

    {
        const float* bp = inA;
        #pragma unroll
        for (int f = 0; f < 7; ++f)
            cp4(smaddr(&patchB[0][0]) + fso[f] * 4, bp + fcp[f] + fgo[f], fva[f]);
        #pragma unroll
        for (int f = 0; f < 3; ++f) {
            int idx = tid + f * 256;
            cp16(smaddr(&wsmB[0][0]) + idx * 16, wT + idx * 4, (f < 2) || (tid < 64));
        }
        cp_commit();
    }

    for (int chunk = 0; chunk < 16; ++chunk) {
        int cur = chunk & 1;
        if (chunk + 1 < 16) {
            int nxt = cur ^ 1;
            int nc = chunk + 1;
            const float* bp = (nc < 8) ? (inA + nc * 8 * HW) : (inB + (nc - 8) * 8 * HW);
            #pragma unroll
            for (int f = 0; f < 7; ++f)
                cp4(smaddr(&patchB[nxt][0]) + fso[f] * 4, bp + fcp[f] + fgo[f], fva[f]);
            const float* wc = wT + nc * 2304;
            #pragma unroll
            for (int f = 0; f < 3; ++f) {
                int idx = tid + f * 256;
                cp16(smaddr(&wsmB[nxt][0]) + idx * 16, wc + idx * 4, (f < 2) || (tid < 64));
            }
            cp_commit();
            cp_wait<1>();
        } else {
            cp_wait<0>();
        }
        __syncthreads();
        const float* patch = patchB[cur];
        const float* wsm = wsmB[cur];
        #pragma unroll
        for (int c = 0; c < 8; ++c) {
            #pragma unroll
            for (int k = 0; k < 9; ++k) {
                const int ky = k / 3, kx = k - ky * 3;
                ulonglong2 wv = *(const ulonglong2*)&wsm[(c * 9 + k) * 32 + (g << 2)];
                #pragma unroll
                for (int ry = 0; ry < 4; ++ry) {
                    float iv = patch[(c * 6 + ry + ky) * 34 + col + kx];
                    ull iv2 = pk2(iv, iv);
                    ffma2(acc[ry][0], iv2, wv.x);
                    ffma2(acc[ry][1], iv2, wv.y);
                }
            }
        }
        __syncthreads();
    }
    int oc0 = g << 2;
    int x0 = bx * 32 + col;
    #pragma unroll
    for (int pj = 0; pj < 2; ++pj) {
        #pragma unroll
        for (int ry = 0; ry < 4; ++ry) {
            float v0, v1;
            upk2(acc[ry][pj], v0, v1);
            float vv[2] = {v0, v1};
            #pragma unroll
            for (int h = 0; h < 2; ++h) {
                int oc = oc0 + pj * 2 + h;
                if (oc < 18) {
                    float v = vv[h] + off_b[i * 18 + oc];
                    v = fminf(fmaxf(v, -32.f), 32.f);
                    g_off[((i * BATCH + b) * 18 + oc) * HW + (by * 4 + ry) * 128 + x0] = v;
                } else if (oc < 27) {
                    float t = vv[h] + mod_b[i * 9 + (oc - 18)];
                    g_mod[((i * BATCH + b) * 9 + (oc - 18)) * HW + (by * 4 + ry) * 128 + x0]
                        = 2.f / (1.f + expf(-t));
                }
            }
        }
    }
}

// ---------------- deformable conv (emits packed attention planes) ------------
__global__ void __launch_bounds__(256) deform_kernel(const float* __restrict__ reg_b) {
    extern __shared__ __align__(16) float sm[];
    float* samp = sm;
    float* wsmB0 = sm + 8192;
    float* wsmB1 = sm + 12288;
    int tid = threadIdx.x;
    int bx = blockIdx.x, by = blockIdx.y, b = blockIdx.z;
    int g = tid >> 5, col = tid & 31;
    ull acc[4][4];
    #pragma unroll
    for (int a = 0; a < 4; ++a)
        #pragma unroll
        for (int o = 0; o < 4; ++o) acc[a][o] = 0ull;
    int p = tid & 127;
    int chalf = tid >> 7;
    int py_ = by * 4 + (p >> 5);
    int px_ = bx * 32 + (p & 31);
    int po = py_ * 128 + px_;

    {
        const float* wb = g_wreg;
        #pragma unroll
        for (int f = 0; f < 4; ++f) {
            int idx = tid + f * 256;
            int c = idx >> 4, q = idx & 15;
            cp16(smaddr(wsmB0) + idx * 16, wb + (c * 9 + 0) * 64 + q * 4, 1);
        }
        cp_commit();
    }

    for (int it = 0; it < 27; ++it) {
        int i = it / 9, kk = it - i * 9;
        const float* refb = g_ref + (i * BATCH + b) * NF * HW;
        const float* offb = g_off + (i * BATCH + b) * 18 * HW;
        const float* modb = g_mod + (i * BATCH + b) * 9 * HW;

        float dy = offb[(2 * kk) * HW + po];
        float dx = offb[(2 * kk + 1) * HW + po];
        float m  = modb[kk * HW + po];
        float py = (float)(py_ + kk / 3 - 1) + dy;
        float px = (float)(px_ + kk % 3 - 1) + dx;
        float fy = floorf(py), fx = floorf(px);
        float ty = py - fy, tx = px - fx;
        int iy0 = (int)fy, ix0 = (int)fx;
        int iy1 = iy0 + 1, ix1 = ix0 + 1;
        float vy0 = ((unsigned)iy0 < 128u) ? 1.f : 0.f;
        float vy1 = ((unsigned)iy1 < 128u) ? 1.f : 0.f;
        float vx0 = ((unsigned)ix0 < 128u) ? 1.f : 0.f;
        float vx1 = ((unsigned)ix1 < 128u) ? 1.f : 0.f;
        float f00 = (1.f - ty) * (1.f - tx) * m * vy0 * vx0;
        float f01 = (1.f - ty) * tx * m * vy0 * vx1;
        float f10 = ty * (1.f - tx) * m * vy1 * vx0;
        float f11 = ty * tx * m * vy1 * vx1;
        int r0 = min(max(iy0, 0), 127) * 128;
        int r1 = min(max(iy1, 0), 127) * 128;
        int c0 = min(max(ix0, 0), 127);
        int c1 = min(max(ix1, 0), 127);

        __syncthreads();
        {
            const float* rbase = refb + chalf * 32 * HW;
            #pragma unroll 4
            for (int j = 0; j < 32; ++j) {
                const float* rc = rbase + j * HW;
                float v = f00 * rc[r0 + c0] + f01 * rc[r0 + c1] +
                          f10 * rc[r1 + c0] + f11 * rc[r1 + c1];
                samp[(chalf * 32 + j) * 128 + p] = v;
            }
        }
        float* wcur = (it & 1) ? wsmB1 : wsmB0;
        if (it + 1 < 27) {
            int nit = it + 1;
            int ni = nit / 9, nkk = nit - ni * 9;
            const float* wb = g_wreg + ni * (64 * 9 * 64);
            float* wnxt = (it & 1) ? wsmB0 : wsmB1;
            #pragma unroll
            for (int f = 0; f < 4; ++f) {
                int idx = tid + f * 256;
                int c = idx >> 4, q = idx & 15;
                cp16(smaddr(wnxt) + idx * 16, wb + (c * 9 + nkk) * 64 + q * 4, 1);
            }
            cp_commit();
            cp_wait<1>();
        } else {
            cp_wait<0>();
        }
        __syncthreads();
        #pragma unroll 4
        for (int c = 0; c < 64; ++c) {
            const ulonglong2* wp = (const ulonglong2*)(wcur + c * 64 + (g << 3));
            ulonglong2 wa = wp[0];
            ulonglong2 wb2 = wp[1];
            float sv0 = samp[c * 128 + col];
            float sv1 = samp[c * 128 + 32 + col];
            float sv2 = samp[c * 128 + 64 + col];
            float sv3 = samp[c * 128 + 96 + col];
            ull s0 = pk2(sv0, sv0), s1 = pk2(sv1, sv1);
            ull s2 = pk2(sv2, sv2), s3 = pk2(sv3, sv3);
            ffma2(acc[0][0], s0, wa.x); ffma2(acc[0][1], s0, wa.y);
            ffma2(acc[0][2], s0, wb2.x); ffma2(acc[0][3], s0, wb2.y);
            ffma2(acc[1][0], s1, wa.x); ffma2(acc[1][1], s1, wa.y);
            ffma2(acc[1][2], s1, wb2.x); ffma2(acc[1][3], s1, wb2.y);
            ffma2(acc[2][0], s2, wa.x); ffma2(acc[2][1], s2, wa.y);
            ffma2(acc[2][2], s2, wb2.x); ffma2(acc[2][3], s2, wb2.y);
            ffma2(acc[3][0], s3, wa.x); ffma2(acc[3][1], s3, wa.y);
            ffma2(acc[3][2], s3, wb2.x); ffma2(acc[3][3], s3, wb2.y);
        }
    }
    __syncthreads();
    int oc0 = g << 3;
    int x0 = bx * 32 + col;
    #pragma unroll
    for (int pj = 0; pj < 4; ++pj) {
        #pragma unroll
        for (int ry = 0; ry < 4; ++ry) {
            float v0, v1;
            upk2(acc[ry][pj], v0, v1);
            int oc = oc0 + pj * 2;
            float r0 = v0 + reg_b[oc] + reg_b[64 + oc] + reg_b[128 + oc];
            float r1 = v1 + reg_b[oc + 1] + reg_b[64 + oc + 1] + reg_b[128 + oc + 1];
            int pix = (by * 4 + ry) * 128 + x0;
            unsigned hi, lo;
            packHL(r0, r1, hi, lo);
            unsigned wadr = ((unsigned)b * HW + pix) * 32 + (oc >> 1);
            g_pVhi[wadr] = hi;
            g_pVlo[wadr] = lo;
        }
    }
}

// ---------------- rb conv: 2 rows/block, barrier-free mainloop ---------------
__global__ void __launch_bounds__(512) rbmma2_kernel(const unsigned* __restrict__ inHi,
                                                     const unsigned* __restrict__ inLo,
                                                     const unsigned* __restrict__ wbimg,
                                                     const float* __restrict__ bias,
                                                     const float* __restrict__ residF,
                                                     float* __restrict__ outF,
                                                     unsigned* __restrict__ outHi,
                                                     unsigned* __restrict__ outLo,
                                                     int doRelu) {
    extern __shared__ __align__(16) unsigned rsm[];
    unsigned* rowHi = rsm;            // 4 slots x 136 x 32 = 17408 words
    unsigned* rowLo = rsm + 17408;
    int tid = threadIdx.x;
    int lane = tid & 31, w = tid >> 5;
    int w8 = w & 7, rowi = w >> 3;
    int y0 = blockIdx.x * 2;
    int b = blockIdx.y;
    unsigned baseb = (unsigned)b * HW * 32;

    // zero border cols (0, 129..135) for 4 slots, both planes
    #pragma unroll
    for (int f = 0; f < 4; ++f) {
        int idx = tid + f * 512;
        int plane = idx >> 10;
        int rem = idx & 1023;
        int s = rem >> 8;
        int rem2 = rem & 255;
        int bc = rem2 >> 5;
        int colc = bc ? (128 + bc) : 0;
        int wadr = (s * 136 + colc) * 32 + (rem2 & 31);
        (plane ? rowLo : rowHi)[wadr] = 0u;
    }
    for (int s = 0; s < 4; ++s) {
        int yy = y0 + s - 1;
        if ((unsigned)yy < 128u) {
            const unsigned* srcH = inHi + baseb + (unsigned)yy * 128 * 32;
            const unsigned* srcL = inLo + baseb + (unsigned)yy * 128 * 32;
            #pragma unroll
            for (int f = 0; f < 2; ++f) {
                int idx = tid + f * 512;
                int xcol = 1 + (idx >> 3);
                int j4 = (idx & 7) << 2;
                int dstw = (s * 136 + xcol) * 32 + (j4 ^ ((xcol & 7) << 2));
                cp16(smaddr(rowHi) + dstw * 4, srcH + (xcol - 1) * 32 + j4, 1);
                cp16(smaddr(rowLo) + dstw * 4, srcL + (xcol - 1) * 32 + j4, 1);
            }
        } else {
            #pragma unroll
            for (int f = 0; f < 9; ++f) {
                int idx = tid + f * 512;
                if (idx < 4352) {
                    rowHi[s * 4352 + idx] = 0u;
                    rowLo[s * 4352 + idx] = 0u;
                }
            }
        }
    }
    cp_commit();

    int m0 = (w8 >> 1) * 32;
    int oc0 = (w8 & 1) * 32;
    int lrow = lane & 7, mi = lane >> 3;
    int qq = lane & 3, rr = lane >> 2;

    int jbase0 = m0 + lrow + ((mi & 1) << 3);
    // B fragment word bases (plain layout): per nt, word = oc*32 + qq
    int bb[4];
    #pragma unroll
    for (int nt = 0; nt < 4; ++nt) bb[nt] = (oc0 + nt * 8 + rr) * 32 + qq;

    float acc[2][4][4];
    #pragma unroll
    for (int mt = 0; mt < 2; ++mt)
        #pragma unroll
        for (int nt = 0; nt < 4; ++nt)
            #pragma unroll
            for (int e = 0; e < 4; ++e) acc[mt][nt][e] = 0.f;

    unsigned rowHiA = smaddr(rowHi);
    unsigned rowLoA = smaddr(rowLo);

    cp_wait<0>();
    __syncthreads();          // ONLY barrier: rows ready; mainloop is sync-free

    for (int tap = 0; tap < 9; ++tap) {
        const unsigned* wt0 = wbimg + tap * 4096;        // hi part
        const unsigned* wt1 = wt0 + 2048;                // lo part
        int slot = tap / 3, dxo = tap - slot * 3;
        int srow = (rowi + slot) * 136;

        #pragma unroll
        for (int chunk = 0; chunk < 4; ++chunk) {
            unsigned aH[2][4], aL[2][4];
            #pragma unroll
            for (int mt = 0; mt < 2; ++mt) {
                int m = jbase0 + mt * 16 + dxo;
                int gA = chunk * 2 + (mi >> 1);
                unsigned wd = (unsigned)((srow + m) * 32 + ((gA ^ (m & 7)) << 2)) * 4u;
                ldsm4(aH[mt], rowHiA + wd);
                ldsm4(aL[mt], rowLoA + wd);
            }
            unsigned bh0[4], bh1[4], bl0[4], bl1[4];
            #pragma unroll
            for (int nt = 0; nt < 4; ++nt) {
                int o = bb[nt] + 8 * chunk;
                bh0[nt] = __ldg(wt0 + o);
                bh1[nt] = __ldg(wt0 + o + 4);
                bl0[nt] = __ldg(wt1 + o);
                bl1[nt] = __ldg(wt1 + o + 4);
            }
            #pragma unroll
            for (int nt = 0; nt < 4; ++nt)
                #pragma unroll
                for (int mt = 0; mt < 2; ++mt)
                    mma_bf16(acc[mt][nt], aH[mt], bh0[nt], bh1[nt]);
            #pragma unroll
            for (int nt = 0; nt < 4; ++nt)
                #pragma unroll
                for (int mt = 0; mt < 2; ++mt)
                    mma_bf16(acc[mt][nt], aL[mt], bh0[nt], bh1[nt]);
            #pragma unroll
            for (int nt = 0; nt < 4; ++nt)
                #pragma unroll
                for (int mt = 0; mt < 2; ++mt)
                    mma_bf16(acc[mt][nt], aH[mt], bl0[nt], bl1[nt]);
        }
    }

    int y = y0 + rowi;
    #pragma unroll
    for (int mt = 0; mt < 2; ++mt) {
        #pragma unroll
        for (int nt = 0; nt < 4; ++nt) {
            int px0 = m0 + mt * 16 + rr;
            int oc = oc0 + nt * 8 + 2 * qq;
            float bv0 = bias[oc], bv1 = bias[oc + 1];
            #pragma unroll
            for (int half = 0; half < 2; ++half) {
                int px = px0 + half * 8;
                float v0 = acc[mt][nt][half * 2 + 0] + bv0;
                float v1 = acc[mt][nt][half * 2 + 1] + bv1;
                if (doRelu) { v0 = fmaxf(v0, 0.f); v1 = fmaxf(v1, 0.f); }
                int oi0 = (b * NF + oc) * HW + y * 128 + px;
                if (residF) { v0 += residF[oi0]; v1 += residF[oi0 + HW]; }
                if (outF) { outF[oi0] = v0; outF[oi0 + HW] = v1; }
                if (outHi) {
                    unsigned hi, lo;
                    packHL(v0, v1, hi, lo);
                    unsigned wadr = (baseb + (unsigned)(y * 128 + px) * 32) + (oc >> 1);
                    outHi[wadr] = hi;
                    outLo[wadr] = lo;
                }
            }
        }
    }
}

// ---------------- fuse conv: 2-set packed HMMA (K=128), LDG weights ----------
__global__ void __launch_bounds__(256) rbmma3_kernel(const float* __restrict__ bias,
                                                     const float* __restrict__ residF,
                                                     float* __restrict__ outF,
                                                     unsigned* __restrict__ outHi,
                                                     unsigned* __restrict__ outLo) {
    extern __shared__ __align__(16) unsigned rsm[];
    unsigned* rowHi = rsm;
    unsigned* rowLo = rsm + 13056;
    int tid = threadIdx.x;
    int lane = tid & 31, w = tid >> 5;
    int y = blockIdx.x;
    int b = blockIdx.y;
    unsigned baseb = (unsigned)b * HW * 32;

    #pragma unroll
    for (int f = 0; f < 3; ++f) {
        int idx = tid + f * 256;
        int s = idx >> 8;
        int rem = idx & 255;
        int bc = rem >> 5;
        int colc = bc ? (128 + bc) : 0;
        int wadr = (s * 136 + colc) * 32 + (rem & 31);
        rowHi[wadr] = 0u;
        rowLo[wadr] = 0u;
    }
    for (int s = 0; s < 3; ++s) {
        int yy = y + s - 1;
        if ((unsigned)yy < 128u) {
            const unsigned* srcH = g_pUhi + baseb + (unsigned)yy * 128 * 32;
            const unsigned* srcL = g_pUlo + baseb + (unsigned)yy * 128 * 32;
            #pragma unroll
            for (int f = 0; f < 4; ++f) {
                int idx = tid + f * 256;
                int xcol = 1 + (idx >> 3);
                int j4 = (idx & 7) << 2;
                int dstw = (s * 136 + xcol) * 32 + (j4 ^ ((xcol & 7) << 2));
                cp16(smaddr(rowHi) + dstw * 4, srcH + (xcol - 1) * 32 + j4, 1);
                cp16(smaddr(rowLo) + dstw * 4, srcL + (xcol - 1) * 32 + j4, 1);
            }
        } else {
            #pragma unroll
            for (int f = 0; f < 17; ++f) {
                int idx = tid + f * 256;
                int wadr = s * 136 * 32 + idx;
                rowHi[wadr] = 0u;
                rowLo[wadr] = 0u;
            }
        }
    }
    cp_commit();

    int m0 = (w >> 1) * 32;
    int oc0 = (w & 1) * 32;
    int lrow = lane & 7, mi = lane >> 3;
    int qq = lane & 3, rr = lane >> 2;
    int jbase0 = m0 + lrow + ((mi & 1) << 3);
    int bb[4];
    #pragma unroll
    for (int nt = 0; nt < 4; ++nt) bb[nt] = (oc0 + nt * 8 + rr) * 32 + qq;

    float acc[2][4][4];
    #pragma unroll
    for (int mt = 0; mt < 2; ++mt)
        #pragma unroll
        for (int nt = 0; nt < 4; ++nt)
            #pragma unroll
            for (int e = 0; e < 4; ++e) acc[mt][nt][e] = 0.f;

    unsigned rowHiA = smaddr(rowHi);
    unsigned rowLoA = smaddr(rowLo);

    cp_wait<0>();
    __syncthreads();

    for (int it = 0; it < 18; ++it) {
        if (it == 9) {
            __syncthreads();   // all warps done reading set0 rows
            for (int s = 0; s < 3; ++s) {
                int yy = y + s - 1;
                if ((unsigned)yy < 128u) {
                    const unsigned* srcH = g_pVhi + baseb + (unsigned)yy * 128 * 32;
                    const unsigned* srcL = g_pVlo + baseb + (unsigned)yy * 128 * 32;
                    #pragma unroll
                    for (int f = 0; f < 4; ++f) {
                        int idx = tid + f * 256;
                        int xcol = 1 + (idx >> 3);
                        int j4 = (idx & 7) << 2;
                        int dstw = (s * 136 + xcol) * 32 + (j4 ^ ((xcol & 7) << 2));
                        cp16(smaddr(rowHi) + dstw * 4, srcH + (xcol - 1) * 32 + j4, 1);
                        cp16(smaddr(rowLo) + dstw * 4, srcL + (xcol - 1) * 32 + j4, 1);
                    }
                }
            }
            cp_commit();
            cp_wait<0>();
            __syncthreads();
        }
        const unsigned* wt0 = g_wfb + it * 4096;
        const unsigned* wt1 = wt0 + 2048;
        int tap = (it < 9) ? it : (it - 9);
        int slot = tap / 3, dxo = tap - slot * 3;
        int srow = slot * 136;

        #pragma unroll
        for (int chunk = 0; chunk < 4; ++chunk) {
            unsigned aH[2][4], aL[2][4];
            #pragma unroll
            for (int mt = 0; mt < 2; ++mt) {
                int m = jbase0 + mt * 16 + dxo;
                int gA = chunk * 2 + (mi >> 1);
                unsigned wd = (unsigned)((srow + m) * 32 + ((gA ^ (m & 7)) << 2)) * 4u;
                ldsm4(aH[mt], rowHiA + wd);
                ldsm4(aL[mt], rowLoA + wd);
            }
            unsigned bh0[4], bh1[4], bl0[4], bl1[4];
            #pragma unroll
            for (int nt = 0; nt < 4; ++nt) {
                int o = bb[nt] + 8 * chunk;
                bh0[nt] = __ldg(wt0 + o);
                bh1[nt] = __ldg(wt0 + o + 4);
                bl0[nt] = __ldg(wt1 + o);
                bl1[nt] = __ldg(wt1 + o + 4);
            }
            #pragma unroll
            for (int nt = 0; nt < 4; ++nt)
                #pragma unroll
                for (int mt = 0; mt < 2; ++mt)
                    mma_bf16(acc[mt][nt], aH[mt], bh0[nt], bh1[nt]);
            #pragma unroll
            for (int nt = 0; nt < 4; ++nt)
                #pragma unroll
                for (int mt = 0; mt < 2; ++mt)
                    mma_bf16(acc[mt][nt], aL[mt], bh0[nt], bh1[nt]);
            #pragma unroll
            for (int nt = 0; nt < 4; ++nt)
                #pragma unroll
                for (int mt = 0; mt < 2; ++mt)
                    mma_bf16(acc[mt][nt], aH[mt], bl0[nt], bl1[nt]);
        }
    }

    #pragma unroll
    for (int mt = 0; mt < 2; ++mt) {
        #pragma unroll
        for (int nt = 0; nt < 4; ++nt) {
            int px0 = m0 + mt * 16 + rr;
            int oc = oc0 + nt * 8 + 2 * qq;
            float bv0 = bias[oc], bv1 = bias[oc + 1];
            #pragma unroll
            for (int half = 0; half < 2; ++half) {
                int px = px0 + half * 8;
                float v0 = acc[mt][nt][half * 2 + 0] + bv0;
                float v1 = acc[mt][nt][half * 2 + 1] + bv1;
                int oi0 = (b * NF + oc) * HW + y * 128 + px;
                v0 += residF[oi0];
                v1 += residF[oi0 + HW];
                outF[oi0] = v0;
                outF[oi0 + HW] = v1;
                unsigned hi, lo;
                packHL(v0, v1, hi, lo);
                unsigned wadr = (baseb + (unsigned)(y * 128 + px) * 32) + (oc >> 1);
                outHi[wadr] = hi;
                outLo[wadr] = lo;
            }
        }
    }
}

// ---------------- host launcher ----------------------------------------------
extern "C" void kernel_launch(void* const* d_in, const int* in_sizes, int n_in,
                              void* d_out, int out_size) {
    (void)in_sizes; (void)n_in; (void)out_size;
    const float* x      = (const float*)d_in[0];
    const float* T      = (const float*)d_in[1];
    const float* S      = (const float*)d_in[2];
    const float* off_w  = (const float*)d_in[3];
    const float* off_b  = (const float*)d_in[4];
    const float* mod_w  = (const float*)d_in[5];
    const float* mod_b  = (const float*)d_in[6];
    const float* reg_w  = (const float*)d_in[7];
    const float* reg_b  = (const float*)d_in[8];
    const float* fuse_w = (const float*)d_in[9];
    const float* fuse_b = (const float*)d_in[10];
    const float* rb_w1  = (const float*)d_in[11];
    const float* rb_b1  = (const float*)d_in[12];
    const float* rb_w2  = (const float*)d_in[13];
    const float* rb_b2  = (const float*)d_in[14];
    float* out = (float*)d_out;

    const int DEFORM_SMEM = (8192 + 2 * 4096) * 4;
    const int RB2_SMEM    = (2 * 17408) * 4;             // 139264 B
    const int RB3_SMEM    = (2 * 13056) * 4;             // 104448 B
    cudaFuncSetAttribute(deform_kernel, cudaFuncAttributeMaxDynamicSharedMemorySize, DEFORM_SMEM);
    cudaFuncSetAttribute(rbmma2_kernel, cudaFuncAttributeMaxDynamicSharedMemorySize, RB2_SMEM);
    cudaFuncSetAttribute(rbmma3_kernel, cudaFuncAttributeMaxDynamicSharedMemorySize, RB3_SMEM);

    float *wreg, *xA;
    unsigned *wbm1, *wbm2, *pXhi, *pXlo, *pThi, *pTlo;
    cudaGetSymbolAddress((void**)&wreg,  g_wreg);
    cudaGetSymbolAddress((void**)&wbm1,  g_wbm1);
    cudaGetSymbolAddress((void**)&wbm2,  g_wbm2);
    cudaGetSymbolAddress((void**)&xA,    g_xA);
    cudaGetSymbolAddress((void**)&pXhi,  g_pXhi);
    cudaGetSymbolAddress((void**)&pXlo,  g_pXlo);
    cudaGetSymbolAddress((void**)&pThi,  g_pThi);
    cudaGetSymbolAddress((void**)&pTlo,  g_pTlo);

    sup_kernel<<<(TOPK * BATCH * HW + 255) / 256, 256>>>(S);
    ref_kernel<<<(TOPK * BATCH * NF * HW / 4 + 255) / 256, 256>>>(T);
    {
        int tot = 8 * 9 * 64 * 32;
        wt_wbm<<<(tot + 255) / 256, 256>>>(rb_w1, wbm1);
        wt_wbm<<<(tot + 255) / 256, 256>>>(rb_w2, wbm2);
    }
    {
        int tot = TOPK * 128 * 9 * 32;
        wt_om<<<(tot + 255) / 256, 256>>>(off_w, mod_w);
    }
    {
        int tot = TOPK * 64 * 9 * 64;
        wt_generic<<<(tot + 255) / 256, 256>>>(reg_w, wreg, 64, 64, 64, tot);
    }
    {
        int tot = 2 * 9 * 64 * 32;
        wt_wfb<<<(tot + 255) / 256, 256>>>(fuse_w);
    }
    pack_x<<<(BATCH * HW * 32 + 255) / 256, 256>>>(x);
    convom_kernel<<<dim3(4, 32, 12), 256>>>(x, off_b, mod_b);
    deform_kernel<<<dim3(4, 32, 4), 256, DEFORM_SMEM>>>(reg_b);
    rbmma3_kernel<<<dim3(128, 4), 256, RB3_SMEM>>>(fuse_b, x, xA, pXhi, pXlo);

    for (int r = 0; r < 8; ++r) {
        rbmma2_kernel<<<dim3(64, 4), 512, RB2_SMEM>>>(pXhi, pXlo, wbm1 + r * 36864,
                                                      rb_b1 + r * 64,
                                                      (const float*)0, (float*)0,
                                                      pThi, pTlo, 1);
        float* o = (r == 7) ? out : xA;
        rbmma2_kernel<<<dim3(64, 4), 512, RB2_SMEM>>>(pThi, pTlo, wbm2 + r * 36864,
                                                      rb_b2 + r * 64,
                                                      xA, o,
                                                      (r == 7) ? (unsigned*)0 : pXhi,
                                                      (r == 7) ? (unsigned*)0 : pXlo, 0);
    }
}

// round 17
// speedup vs baseline: 1.6340x; 1.6340x over previous
#include <cuda_runtime.h>
#include <math.h>

#define H 128
#define W 128
#define HW 16384
#define BATCH 4
#define NF 64
#define TOPK 3

typedef unsigned long long ull;

__device__ __forceinline__ ull pk2(float a, float b) {
    ull r; asm("mov.b64 %0,{%1,%2};" : "=l"(r) : "f"(a), "f"(b)); return r;
}
__device__ __forceinline__ void upk2(ull v, float& a, float& b) {
    asm("mov.b64 {%0,%1},%2;" : "=f"(a), "=f"(b) : "l"(v));
}
__device__ __forceinline__ void ffma2(ull& d, ull a, ull b) {
    asm("fma.rn.f32x2 %0,%1,%2,%0;" : "+l"(d) : "l"(a), "l"(b));
}
__device__ __forceinline__ unsigned smaddr(const void* p) {
    return (unsigned)__cvta_generic_to_shared(p);
}
__device__ __forceinline__ void cp4(unsigned s, const void* g, int pred) {
    asm volatile("{\n\t.reg .pred p;\n\tsetp.ne.u32 p,%2,0;\n\t"
                 "@p cp.async.ca.shared.global [%0],[%1],4;\n\t}"
                 :: "r"(s), "l"(g), "r"(pred));
}
__device__ __forceinline__ void cp16(unsigned s, const void* g, int pred) {
    asm volatile("{\n\t.reg .pred p;\n\tsetp.ne.u32 p,%2,0;\n\t"
                 "@p cp.async.cg.shared.global [%0],[%1],16;\n\t}"
                 :: "r"(s), "l"(g), "r"(pred));
}
__device__ __forceinline__ void cp_commit() { asm volatile("cp.async.commit_group;"); }
template<int N> __device__ __forceinline__ void cp_wait() {
    asm volatile("cp.async.wait_group %0;" :: "n"(N));
}

__device__ __forceinline__ unsigned bf16pack(float v0, float v1) {
    unsigned r;
    asm("cvt.rn.satfinite.bf16x2.f32 %0,%1,%2;" : "=r"(r) : "f"(v1), "f"(v0));
    return r;
}
__device__ __forceinline__ void packHL(float v0, float v1, unsigned& hi, unsigned& lo) {
    hi = bf16pack(v0, v1);
    float l0 = v0 - __uint_as_float(hi << 16);
    float l1 = v1 - __uint_as_float(hi & 0xffff0000u);
    lo = bf16pack(l0, l1);
}

__device__ __forceinline__ void mma_bf16(float* d, const unsigned* a, unsigned b0, unsigned b1) {
    asm("mma.sync.aligned.m16n8k16.row.col.f32.bf16.bf16.f32 "
        "{%0,%1,%2,%3}, {%4,%5,%6,%7}, {%8,%9}, {%0,%1,%2,%3};"
        : "+f"(d[0]), "+f"(d[1]), "+f"(d[2]), "+f"(d[3])
        : "r"(a[0]), "r"(a[1]), "r"(a[2]), "r"(a[3]), "r"(b0), "r"(b1));
}
__device__ __forceinline__ void ldsm4(unsigned* r, unsigned addr) {
    asm volatile("ldmatrix.sync.aligned.m8n8.x4.shared.b16 {%0,%1,%2,%3}, [%4];"
                 : "=r"(r[0]), "=r"(r[1]), "=r"(r[2]), "=r"(r[3]) : "r"(addr));
}

// ---------------- device global scratch --------------------------------------
static __device__ float g_sup [TOPK*BATCH*HW];
static __device__ float g_ref [TOPK*BATCH*NF*HW];
static __device__ float g_off [TOPK*BATCH*18*HW];
static __device__ float g_mod [TOPK*BATCH*9*HW];
static __device__ float g_xA  [BATCH*NF*HW];
static __device__ float g_wreg[TOPK*64*9*64];
static __device__ unsigned g_wbm1[8*36864];   // swizzled [conv][tap][part][oc64][32]
static __device__ unsigned g_wbm2[8*36864];
static __device__ unsigned g_wfb [73728];     // swizzled fuse [18 it][part][oc64][32]
static __device__ unsigned g_wcb [TOPK*36864];// swizzled convom [i][18 it][part][oc32][32]
static __device__ unsigned g_pXhi[BATCH*HW*32];
static __device__ unsigned g_pXlo[BATCH*HW*32];
static __device__ unsigned g_pThi[BATCH*HW*32];
static __device__ unsigned g_pTlo[BATCH*HW*32];
static __device__ unsigned g_pUhi[BATCH*HW*32];
static __device__ unsigned g_pUlo[BATCH*HW*32];
static __device__ unsigned g_pVhi[BATCH*HW*32];
static __device__ unsigned g_pVlo[BATCH*HW*32];
static __device__ unsigned g_pRhi[TOPK*BATCH*HW*32];
static __device__ unsigned g_pRlo[TOPK*BATCH*HW*32];

// ---------------- weight transposes ------------------------------------------
__global__ void wt_generic(const float* __restrict__ src, float* __restrict__ dst,
                           int O, int C, int OP, int total) {
    int idx = blockIdx.x * blockDim.x + threadIdx.x;
    if (idx >= total) return;
    int per = C * 9 * OP;
    int s = idx / per;
    int r = idx - s * per;
    int c = r / (9 * OP);
    int r2 = r - c * (9 * OP);
    int k = r2 / OP;
    int o = r2 - k * OP;
    dst[idx] = (o < O) ? src[((s * O + o) * C + c) * 9 + k] : 0.f;
}

// rb weights -> bf16 hi/lo swizzled pairs (R15 layout)
__global__ void wt_wbm(const float* __restrict__ src, unsigned* __restrict__ dst) {
    int idx = blockIdx.x * blockDim.x + threadIdx.x;
    const int total = 8 * 9 * 64 * 32;
    if (idx >= total) return;
    int conv = idx / 18432;
    int r = idx - conv * 18432;
    int tap = r / 2048;
    int r2 = r - tap * 2048;
    int oc = r2 >> 5;
    int p = r2 & 31;
    int c = 2 * p;
    float v0 = src[((conv * 64 + oc) * 64 + c) * 9 + tap];
    float v1 = src[((conv * 64 + oc) * 64 + c + 1) * 9 + tap];
    unsigned hi, lo;
    packHL(v0, v1, hi, lo);
    int pp = p ^ ((oc & 7) << 2);
    dst[(((conv * 9 + tap) * 2 + 0) * 64 + oc) * 32 + pp] = hi;
    dst[(((conv * 9 + tap) * 2 + 1) * 64 + oc) * 32 + pp] = lo;
}

// fuse weights -> swizzled 18 (half,tap) images (R15 layout)
__global__ void wt_wfb(const float* __restrict__ src) {
    int idx = blockIdx.x * blockDim.x + threadIdx.x;
    const int total = 2 * 9 * 64 * 32;
    if (idx >= total) return;
    int h = idx / 18432;
    int r = idx - h * 18432;
    int tap = r / 2048;
    int r2 = r - tap * 2048;
    int oc = r2 >> 5;
    int p = r2 & 31;
    int c = h * 64 + 2 * p;
    float v0 = src[(oc * 128 + c) * 9 + tap];
    float v1 = src[(oc * 128 + c + 1) * 9 + tap];
    unsigned hi, lo;
    packHL(v0, v1, hi, lo);
    int pp = p ^ ((oc & 7) << 2);
    g_wfb[(((h * 9 + tap) * 2 + 0) * 64 + oc) * 32 + pp] = hi;
    g_wfb[(((h * 9 + tap) * 2 + 1) * 64 + oc) * 32 + pp] = lo;
}

// convom weights (off 18 + mod 9, padded to 32 oc) -> swizzled per-i images
__global__ void wt_womb(const float* __restrict__ offw, const float* __restrict__ modw) {
    int idx = blockIdx.x * blockDim.x + threadIdx.x;
    const int total = TOPK * 18 * 32 * 32;
    if (idx >= total) return;
    int i = idx / 18432;
    int r = idx - i * 18432;
    int it = r / 1024;
    int r2 = r - it * 1024;
    int oc = r2 >> 5;
    int p = r2 & 31;
    int half = it / 9, tap = it - half * 9;
    int c = half * 64 + 2 * p;
    float v0 = 0.f, v1 = 0.f;
    if (oc < 18) {
        v0 = offw[((i * 18 + oc) * 128 + c) * 9 + tap];
        v1 = offw[((i * 18 + oc) * 128 + c + 1) * 9 + tap];
    } else if (oc < 27) {
        v0 = modw[((i * 9 + (oc - 18)) * 128 + c) * 9 + tap];
        v1 = modw[((i * 9 + (oc - 18)) * 128 + c + 1) * 9 + tap];
    }
    unsigned hi, lo;
    packHL(v0, v1, hi, lo);
    int pp = p ^ ((oc & 7) << 2);
    g_wcb[(((i * 18 + it) * 2 + 0) * 32 + oc) * 32 + pp] = hi;
    g_wcb[(((i * 18 + it) * 2 + 1) * 32 + oc) * 32 + pp] = lo;
}

__global__ void pack_x(const float* __restrict__ x) {
    int idx = blockIdx.x * blockDim.x + threadIdx.x;
    const int total = BATCH * HW * 32;
    if (idx >= total) return;
    int b = idx / (HW * 32);
    int r = idx - b * (HW * 32);
    int px = r >> 5;
    int cp = r & 31;
    float v0 = x[(b * NF + 2 * cp) * HW + px];
    float v1 = x[(b * NF + 2 * cp + 1) * HW + px];
    unsigned hi, lo;
    packHL(v0, v1, hi, lo);
    g_pUhi[idx] = hi;
    g_pUlo[idx] = lo;
}

__global__ void pack_ref() {
    int idx = blockIdx.x * blockDim.x + threadIdx.x;
    const int total = TOPK * BATCH * HW * 32;
    if (idx >= total) return;
    int ib = idx / (HW * 32);
    int r = idx - ib * (HW * 32);
    int px = r >> 5;
    int cp = r & 31;
    float v0 = g_ref[(ib * NF + 2 * cp) * HW + px];
    float v1 = g_ref[(ib * NF + 2 * cp + 1) * HW + px];
    unsigned hi, lo;
    packHL(v0, v1, hi, lo);
    g_pRhi[idx] = hi;
    g_pRlo[idx] = lo;
}

// ---------------- bicubic 2x upsample ----------------------------------------
__global__ void sup_kernel(const float* __restrict__ S) {
    int idx = blockIdx.x * blockDim.x + threadIdx.x;
    if (idx >= TOPK * BATCH * HW) return;
    int ib = idx / HW;
    int p = idx & (HW - 1);
    int oy = p >> 7, ox = p & 127;
    const float* s = S + ib * 64 * 64;
    const float wE0 = -0.03515625f, wE1 = 0.26171875f, wE2 = 0.87890625f, wE3 = -0.10546875f;
    float wy[4], wx[4];
    if (oy & 1) { wy[0] = wE3; wy[1] = wE2; wy[2] = wE1; wy[3] = wE0; }
    else        { wy[0] = wE0; wy[1] = wE1; wy[2] = wE2; wy[3] = wE3; }
    if (ox & 1) { wx[0] = wE3; wx[1] = wE2; wx[2] = wE1; wx[3] = wE0; }
    else        { wx[0] = wE0; wx[1] = wE1; wx[2] = wE2; wx[3] = wE3; }
    int iy0 = (int)floorf(0.5f * (float)oy - 0.25f) - 1;
    int ix0 = (int)floorf(0.5f * (float)ox - 0.25f) - 1;
    float acc = 0.f;
    #pragma unroll
    for (int jy = 0; jy < 4; ++jy) {
        int yy = min(max(iy0 + jy, 0), 63);
        float row = 0.f;
        #pragma unroll
        for (int jx = 0; jx < 4; ++jx) {
            int xx = min(max(ix0 + jx, 0), 63);
            row += wx[jx] * s[yy * 64 + xx];
        }
        acc += wy[jy] * row;
    }
    g_sup[idx] = acc;
}

__global__ void ref_kernel(const float* __restrict__ T) {
    int idx = blockIdx.x * blockDim.x + threadIdx.x;
    const int total = TOPK * BATCH * NF * HW / 4;
    if (idx >= total) return;
    int q = idx & 4095;
    int ibc = idx >> 12;
    int ib = ibc / NF;
    float4 t = ((const float4*)T)[idx];
    float4 s = ((const float4*)g_sup)[ib * 4096 + q];
    float4 r;
    r.x = t.x * s.x; r.y = t.y * s.y; r.z = t.z * s.z; r.w = t.w * s.w;
    ((float4*)g_ref)[idx] = r;
}

// ---------------- convom via HMMA (N=32): offset+modulator conv --------------
__global__ void __launch_bounds__(256) convom2_kernel(const float* __restrict__ off_b,
                                                      const float* __restrict__ mod_b) {
    extern __shared__ __align__(16) unsigned rsm[];
    unsigned* rowHi = rsm;            // 3 x 136 x 32 = 13056
    unsigned* rowLo = rsm + 13056;
    unsigned* Bbuf  = rsm + 26112;    // 2 x 2048
    int tid = threadIdx.x;
    int lane = tid & 31, w = tid >> 5;
    int y = blockIdx.x;
    int ib = blockIdx.y;              // i*4 + b
    int i = ib >> 2, b = ib & 3;
    unsigned baseb = (unsigned)b * HW * 32;
    unsigned baser = (unsigned)ib * HW * 32;
    const unsigned* wbase = g_wcb + i * 36864;

    // prefetch it0 weights: 2048 words = 512 cp16
    #pragma unroll
    for (int f = 0; f < 2; ++f) {
        int idx = tid + f * 256;
        cp16(smaddr(Bbuf) + idx * 16, wbase + idx * 4, idx < 512);
    }
    cp_commit();

    #pragma unroll
    for (int f = 0; f < 3; ++f) {
        int idx = tid + f * 256;
        int s = idx >> 8;
        int rem = idx & 255;
        int bc = rem >> 5;
        int colc = bc ? (128 + bc) : 0;
        int wadr = (s * 136 + colc) * 32 + (rem & 31);
        rowHi[wadr] = 0u;
        rowLo[wadr] = 0u;
    }
    for (int s = 0; s < 3; ++s) {
        int yy = y + s - 1;
        if ((unsigned)yy < 128u) {
            const unsigned* srcH = g_pUhi + baseb + (unsigned)yy * 128 * 32;
            const unsigned* srcL = g_pUlo + baseb + (unsigned)yy * 128 * 32;
            #pragma unroll
            for (int f = 0; f < 4; ++f) {
                int idx = tid + f * 256;
                int xcol = 1 + (idx >> 3);
                int j4 = (idx & 7) << 2;
                int dstw = (s * 136 + xcol) * 32 + (j4 ^ ((xcol & 7) << 2));
                cp16(smaddr(rowHi) + dstw * 4, srcH + (xcol - 1) * 32 + j4, 1);
                cp16(smaddr(rowLo) + dstw * 4, srcL + (xcol - 1) * 32 + j4, 1);
            }
        } else {
            #pragma unroll
            for (int f = 0; f < 17; ++f) {
                int idx = tid + f * 256;
                int wadr = s * 136 * 32 + idx;
                rowHi[wadr] = 0u;
                rowLo[wadr] = 0u;
            }
        }
    }
    cp_commit();

    int m0 = (w >> 1) * 32;
    int oc0 = (w & 1) * 16;
    int lrow = lane & 7, mi = lane >> 3;
    int qq = lane & 3, rr = lane >> 2;
    int jbase0 = m0 + lrow + ((mi & 1) << 3);
    int ocb = oc0 + ((mi >> 1) << 3) + lrow;     // 0..31
    unsigned bwordBase[2][4];
    #pragma unroll
    for (int chunk = 0; chunk < 4; ++chunk) {
        int gB = chunk * 2 + (mi & 1);
        unsigned wd = ocb * 32 + ((gB ^ (ocb & 7)) << 2);
        bwordBase[0][chunk] = wd;
        bwordBase[1][chunk] = wd + 1024;
    }

    float acc[2][2][4];
    #pragma unroll
    for (int mt = 0; mt < 2; ++mt)
        #pragma unroll
        for (int nt = 0; nt < 2; ++nt)
            #pragma unroll
            for (int e = 0; e < 4; ++e) acc[mt][nt][e] = 0.f;

    unsigned rowHiA = smaddr(rowHi);
    unsigned rowLoA = smaddr(rowLo);

    for (int it = 0; it < 18; ++it) {
        cp_wait<0>();
        __syncthreads();
        if (it == 9) {
            for (int s = 0; s < 3; ++s) {
                int yy = y + s - 1;
                if ((unsigned)yy < 128u) {
                    const unsigned* srcH = g_pRhi + baser + (unsigned)yy * 128 * 32;
                    const unsigned* srcL = g_pRlo + baser + (unsigned)yy * 128 * 32;
                    #pragma unroll
                    for (int f = 0; f < 4; ++f) {
                        int idx = tid + f * 256;
                        int xcol = 1 + (idx >> 3);
                        int j4 = (idx & 7) << 2;
                        int dstw = (s * 136 + xcol) * 32 + (j4 ^ ((xcol & 7) << 2));
                        cp16(smaddr(rowHi) + dstw * 4, srcH + (xcol - 1) * 32 + j4, 1);
                        cp16(smaddr(rowLo) + dstw * 4, srcL + (xcol - 1) * 32 + j4, 1);
                    }
                }
            }
            cp_commit();
            cp_wait<0>();
            __syncthreads();
        }
        if (it + 1 < 18) {
            unsigned bs = smaddr(Bbuf + ((it + 1) & 1) * 2048);
            const unsigned* src = wbase + (it + 1) * 2048;
            #pragma unroll
            for (int f = 0; f < 2; ++f) {
                int idx = tid + f * 256;
                cp16(bs + idx * 16, src + idx * 4, idx < 512);
            }
            cp_commit();
        }
        unsigned Bb = smaddr(Bbuf) + (it & 1) * 2048 * 4;
        int tap = (it < 9) ? it : (it - 9);
        int slot = tap / 3, dxo = tap - slot * 3;
        int srow = slot * 136;

        #pragma unroll
        for (int chunk = 0; chunk < 4; ++chunk) {
            unsigned aH[2][4], aL[2][4];
            #pragma unroll
            for (int mt = 0; mt < 2; ++mt) {
                int m = jbase0 + mt * 16 + dxo;
                int gA = chunk * 2 + (mi >> 1);
                unsigned wd = (unsigned)((srow + m) * 32 + ((gA ^ (m & 7)) << 2)) * 4u;
                ldsm4(aH[mt], rowHiA + wd);
                ldsm4(aL[mt], rowLoA + wd);
            }
            unsigned bh[4], bl[4];
            ldsm4(bh, Bb + bwordBase[0][chunk] * 4u);
            ldsm4(bl, Bb + bwordBase[1][chunk] * 4u);
            #pragma unroll
            for (int nt = 0; nt < 2; ++nt)
                #pragma unroll
                for (int mt = 0; mt < 2; ++mt)
                    mma_bf16(acc[mt][nt], aH[mt], bh[nt * 2], bh[nt * 2 + 1]);
            #pragma unroll
            for (int nt = 0; nt < 2; ++nt)
                #pragma unroll
                for (int mt = 0; mt < 2; ++mt)
                    mma_bf16(acc[mt][nt], aL[mt], bh[nt * 2], bh[nt * 2 + 1]);
            #pragma unroll
            for (int nt = 0; nt < 2; ++nt)
                #pragma unroll
                for (int mt = 0; mt < 2; ++mt)
                    mma_bf16(acc[mt][nt], aH[mt], bl[nt * 2], bl[nt * 2 + 1]);
        }
    }

    #pragma unroll
    for (int mt = 0; mt < 2; ++mt) {
        #pragma unroll
        for (int nt = 0; nt < 2; ++nt) {
            int px0 = m0 + mt * 16 + rr;
            int oc = oc0 + nt * 8 + 2 * qq;
            #pragma unroll
            for (int half = 0; half < 2; ++half) {
                int px = px0 + half * 8;
                int pix = y * 128 + px;
                float v0 = acc[mt][nt][half * 2 + 0];
                float v1 = acc[mt][nt][half * 2 + 1];
                #pragma unroll
                for (int h = 0; h < 2; ++h) {
                    int o = oc + h;
                    float v = h ? v1 : v0;
                    if (o < 18) {
                        float r = v + off_b[i * 18 + o];
                        r = fminf(fmaxf(r, -32.f), 32.f);
                        g_off[((ib) * 18 + o) * HW + pix] = r;
                    } else if (o < 27) {
                        float t = v + mod_b[i * 9 + (o - 18)];
                        g_mod[((ib) * 9 + (o - 18)) * HW + pix] = 2.f / (1.f + expf(-t));
                    }
                }
            }
        }
    }
}

// ---------------- deformable conv (R15, emits packed attention planes) -------
__global__ void __launch_bounds__(256) deform_kernel(const float* __restrict__ reg_b) {
    extern __shared__ __align__(16) float sm[];
    float* samp = sm;
    float* wsmB0 = sm + 8192;
    float* wsmB1 = sm + 12288;
    int tid = threadIdx.x;
    int bx = blockIdx.x, by = blockIdx.y, b = blockIdx.z;
    int g = tid >> 5, col = tid & 31;
    ull acc[4][4];
    #pragma unroll
    for (int a = 0; a < 4; ++a)
        #pragma unroll
        for (int o = 0; o < 4; ++o) acc[a][o] = 0ull;
    int p = tid & 127;
    int chalf = tid >> 7;
    int py_ = by * 4 + (p >> 5);
    int px_ = bx * 32 + (p & 31);
    int po = py_ * 128 + px_;

    {
        const float* wb = g_wreg;
        #pragma unroll
        for (int f = 0; f < 4; ++f) {
            int idx = tid + f * 256;
            int c = idx >> 4, q = idx & 15;
            cp16(smaddr(wsmB0) + idx * 16, wb + (c * 9 + 0) * 64 + q * 4, 1);
        }
        cp_commit();
    }

    for (int it = 0; it < 27; ++it) {
        int i = it / 9, kk = it - i * 9;
        const float* refb = g_ref + (i * BATCH + b) * NF * HW;
        const float* offb = g_off + (i * BATCH + b) * 18 * HW;
        const float* modb = g_mod + (i * BATCH + b) * 9 * HW;

        float dy = offb[(2 * kk) * HW + po];
        float dx = offb[(2 * kk + 1) * HW + po];
        float m  = modb[kk * HW + po];
        float py = (float)(py_ + kk / 3 - 1) + dy;
        float px = (float)(px_ + kk % 3 - 1) + dx;
        float fy = floorf(py), fx = floorf(px);
        float ty = py - fy, tx = px - fx;
        int iy0 = (int)fy, ix0 = (int)fx;
        int iy1 = iy0 + 1, ix1 = ix0 + 1;
        float vy0 = ((unsigned)iy0 < 128u) ? 1.f : 0.f;
        float vy1 = ((unsigned)iy1 < 128u) ? 1.f : 0.f;
        float vx0 = ((unsigned)ix0 < 128u) ? 1.f : 0.f;
        float vx1 = ((unsigned)ix1 < 128u) ? 1.f : 0.f;
        float f00 = (1.f - ty) * (1.f - tx) * m * vy0 * vx0;
        float f01 = (1.f - ty) * tx * m * vy0 * vx1;
        float f10 = ty * (1.f - tx) * m * vy1 * vx0;
        float f11 = ty * tx * m * vy1 * vx1;
        int r0 = min(max(iy0, 0), 127) * 128;
        int r1 = min(max(iy1, 0), 127) * 128;
        int c0 = min(max(ix0, 0), 127);
        int c1 = min(max(ix1, 0), 127);

        __syncthreads();
        {
            const float* rbase = refb + chalf * 32 * HW;
            #pragma unroll 4
            for (int j = 0; j < 32; ++j) {
                const float* rc = rbase + j * HW;
                float v = f00 * rc[r0 + c0] + f01 * rc[r0 + c1] +
                          f10 * rc[r1 + c0] + f11 * rc[r1 + c1];
                samp[(chalf * 32 + j) * 128 + p] = v;
            }
        }
        float* wcur = (it & 1) ? wsmB1 : wsmB0;
        if (it + 1 < 27) {
            int nit = it + 1;
            int ni = nit / 9, nkk = nit - ni * 9;
            const float* wb = g_wreg + ni * (64 * 9 * 64);
            float* wnxt = (it & 1) ? wsmB0 : wsmB1;
            #pragma unroll
            for (int f = 0; f < 4; ++f) {
                int idx = tid + f * 256;
                int c = idx >> 4, q = idx & 15;
                cp16(smaddr(wnxt) + idx * 16, wb + (c * 9 + nkk) * 64 + q * 4, 1);
            }
            cp_commit();
            cp_wait<1>();
        } else {
            cp_wait<0>();
        }
        __syncthreads();
        #pragma unroll 4
        for (int c = 0; c < 64; ++c) {
            const ulonglong2* wp = (const ulonglong2*)(wcur + c * 64 + (g << 3));
            ulonglong2 wa = wp[0];
            ulonglong2 wb2 = wp[1];
            float sv0 = samp[c * 128 + col];
            float sv1 = samp[c * 128 + 32 + col];
            float sv2 = samp[c * 128 + 64 + col];
            float sv3 = samp[c * 128 + 96 + col];
            ull s0 = pk2(sv0, sv0), s1 = pk2(sv1, sv1);
            ull s2 = pk2(sv2, sv2), s3 = pk2(sv3, sv3);
            ffma2(acc[0][0], s0, wa.x); ffma2(acc[0][1], s0, wa.y);
            ffma2(acc[0][2], s0, wb2.x); ffma2(acc[0][3], s0, wb2.y);
            ffma2(acc[1][0], s1, wa.x); ffma2(acc[1][1], s1, wa.y);
            ffma2(acc[1][2], s1, wb2.x); ffma2(acc[1][3], s1, wb2.y);
            ffma2(acc[2][0], s2, wa.x); ffma2(acc[2][1], s2, wa.y);
            ffma2(acc[2][2], s2, wb2.x); ffma2(acc[2][3], s2, wb2.y);
            ffma2(acc[3][0], s3, wa.x); ffma2(acc[3][1], s3, wa.y);
            ffma2(acc[3][2], s3, wb2.x); ffma2(acc[3][3], s3, wb2.y);
        }
    }
    __syncthreads();
    int oc0 = g << 3;
    int x0 = bx * 32 + col;
    #pragma unroll
    for (int pj = 0; pj < 4; ++pj) {
        #pragma unroll
        for (int ry = 0; ry < 4; ++ry) {
            float v0, v1;
            upk2(acc[ry][pj], v0, v1);
            int oc = oc0 + pj * 2;
            float r0 = v0 + reg_b[oc] + reg_b[64 + oc] + reg_b[128 + oc];
            float r1 = v1 + reg_b[oc + 1] + reg_b[64 + oc + 1] + reg_b[128 + oc + 1];
            int pix = (by * 4 + ry) * 128 + x0;
            unsigned hi, lo;
            packHL(r0, r1, hi, lo);
            unsigned wadr = ((unsigned)b * HW + pix) * 32 + (oc >> 1);
            g_pVhi[wadr] = hi;
            g_pVlo[wadr] = lo;
        }
    }
}

// ---------------- rb conv: 2 rows/block, 512 threads (R15) -------------------
__global__ void __launch_bounds__(512) rbmma2_kernel(const unsigned* __restrict__ inHi,
                                                     const unsigned* __restrict__ inLo,
                                                     const unsigned* __restrict__ wbimg,
                                                     const float* __restrict__ bias,
                                                     const float* __restrict__ residF,
                                                     float* __restrict__ outF,
                                                     unsigned* __restrict__ outHi,
                                                     unsigned* __restrict__ outLo,
                                                     int doRelu) {
    extern __shared__ __align__(16) unsigned rsm[];
    unsigned* rowHi = rsm;
    unsigned* rowLo = rsm + 17408;
    unsigned* Bbuf  = rsm + 34816;
    int tid = threadIdx.x;
    int lane = tid & 31, w = tid >> 5;
    int w8 = w & 7, rowi = w >> 3;
    int y0 = blockIdx.x * 2;
    int b = blockIdx.y;
    unsigned baseb = (unsigned)b * HW * 32;

    #pragma unroll
    for (int f = 0; f < 2; ++f) {
        int idx = tid + f * 512;
        cp16(smaddr(Bbuf) + idx * 16, wbimg + idx * 4, 1);
    }
    cp_commit();

    #pragma unroll
    for (int f = 0; f < 4; ++f) {
        int idx = tid + f * 512;
        int plane = idx >> 10;
        int rem = idx & 1023;
        int s = rem >> 8;
        int rem2 = rem & 255;
        int bc = rem2 >> 5;
        int colc = bc ? (128 + bc) : 0;
        int wadr = (s * 136 + colc) * 32 + (rem2 & 31);
        (plane ? rowLo : rowHi)[wadr] = 0u;
    }
    for (int s = 0; s < 4; ++s) {
        int yy = y0 + s - 1;
        if ((unsigned)yy < 128u) {
            const unsigned* srcH = inHi + baseb + (unsigned)yy * 128 * 32;
            const unsigned* srcL = inLo + baseb + (unsigned)yy * 128 * 32;
            #pragma unroll
            for (int f = 0; f < 2; ++f) {
                int idx = tid + f * 512;
                int xcol = 1 + (idx >> 3);
                int j4 = (idx & 7) << 2;
                int dstw = (s * 136 + xcol) * 32 + (j4 ^ ((xcol & 7) << 2));
                cp16(smaddr(rowHi) + dstw * 4, srcH + (xcol - 1) * 32 + j4, 1);
                cp16(smaddr(rowLo) + dstw * 4, srcL + (xcol - 1) * 32 + j4, 1);
            }
        } else {
            #pragma unroll
            for (int f = 0; f < 9; ++f) {
                int idx = tid + f * 512;
                if (idx < 4352) {
                    rowHi[s * 4352 + idx] = 0u;
                    rowLo[s * 4352 + idx] = 0u;
                }
            }
        }
    }
    cp_commit();

    int m0 = (w8 >> 1) * 32;
    int oc0 = (w8 & 1) * 32;
    int lrow = lane & 7, mi = lane >> 3;

    int jbase0 = m0 + lrow + ((mi & 1) << 3);
    int ocb0 = oc0 + ((mi >> 1) << 3) + lrow;
    unsigned bwordBase[2][2][4];
    #pragma unroll
    for (int np = 0; np < 2; ++np) {
        int oc = ocb0 + np * 16;
        #pragma unroll
        for (int chunk = 0; chunk < 4; ++chunk) {
            int gB = chunk * 2 + (mi & 1);
            unsigned wd = oc * 32 + ((gB ^ (oc & 7)) << 2);
            bwordBase[np][0][chunk] = wd;
            bwordBase[np][1][chunk] = wd + 2048;
        }
    }

    float acc[2][4][4];
    #pragma unroll
    for (int mt = 0; mt < 2; ++mt)
        #pragma unroll
        for (int nt = 0; nt < 4; ++nt)
            #pragma unroll
            for (int e = 0; e < 4; ++e) acc[mt][nt][e] = 0.f;

    unsigned rowHiA = smaddr(rowHi);
    unsigned rowLoA = smaddr(rowLo);

    for (int tap = 0; tap < 9; ++tap) {
        cp_wait<0>();
        __syncthreads();
        if (tap + 1 < 9) {
            unsigned bs = smaddr(Bbuf + ((tap + 1) & 1) * 4096);
            const unsigned* src = wbimg + (tap + 1) * 4096;
            #pragma unroll
            for (int f = 0; f < 2; ++f) {
                int idx = tid + f * 512;
                cp16(bs + idx * 16, src + idx * 4, 1);
            }
            cp_commit();
        }
        unsigned Bb = smaddr(Bbuf) + (tap & 1) * 4096 * 4;
        int slot = tap / 3, dxo = tap - slot * 3;
        int srow = (rowi + slot) * 136;

        #pragma unroll
        for (int chunk = 0; chunk < 4; ++chunk) {
            unsigned aH[2][4], aL[2][4];
            #pragma unroll
            for (int mt = 0; mt < 2; ++mt) {
                int m = jbase0 + mt * 16 + dxo;
                int gA = chunk * 2 + (mi >> 1);
                unsigned wd = (unsigned)((srow + m) * 32 + ((gA ^ (m & 7)) << 2)) * 4u;
                ldsm4(aH[mt], rowHiA + wd);
                ldsm4(aL[mt], rowLoA + wd);
            }
            unsigned bh[2][4], bl[2][4];
            #pragma unroll
            for (int np = 0; np < 2; ++np) {
                ldsm4(bh[np], Bb + bwordBase[np][0][chunk] * 4u);
                ldsm4(bl[np], Bb + bwordBase[np][1][chunk] * 4u);
            }
            #pragma unroll
            for (int np = 0; np < 2; ++np)
                #pragma unroll
                for (int h = 0; h < 2; ++h)
                    #pragma unroll
                    for (int mt = 0; mt < 2; ++mt)
                        mma_bf16(acc[mt][np * 2 + h], aH[mt], bh[np][h * 2], bh[np][h * 2 + 1]);
            #pragma unroll
            for (int np = 0; np < 2; ++np)
                #pragma unroll
                for (int h = 0; h < 2; ++h)
                    #pragma unroll
                    for (int mt = 0; mt < 2; ++mt)
                        mma_bf16(acc[mt][np * 2 + h], aL[mt], bh[np][h * 2], bh[np][h * 2 + 1]);
            #pragma unroll
            for (int np = 0; np < 2; ++np)
                #pragma unroll
                for (int h = 0; h < 2; ++h)
                    #pragma unroll
                    for (int mt = 0; mt < 2; ++mt)
                        mma_bf16(acc[mt][np * 2 + h], aH[mt], bl[np][h * 2], bl[np][h * 2 + 1]);
        }
    }

    int y = y0 + rowi;
    int qq = lane & 3;
    int rr = lane >> 2;
    #pragma unroll
    for (int mt = 0; mt < 2; ++mt) {
        #pragma unroll
        for (int nt = 0; nt < 4; ++nt) {
            int px0 = m0 + mt * 16 + rr;
            int oc = oc0 + nt * 8 + 2 * qq;
            float bv0 = bias[oc], bv1 = bias[oc + 1];
            #pragma unroll
            for (int half = 0; half < 2; ++half) {
                int px = px0 + half * 8;
                float v0 = acc[mt][nt][half * 2 + 0] + bv0;
                float v1 = acc[mt][nt][half * 2 + 1] + bv1;
                if (doRelu) { v0 = fmaxf(v0, 0.f); v1 = fmaxf(v1, 0.f); }
                int oi0 = (b * NF + oc) * HW + y * 128 + px;
                if (residF) { v0 += residF[oi0]; v1 += residF[oi0 + HW]; }
                if (outF) { outF[oi0] = v0; outF[oi0 + HW] = v1; }
                if (outHi) {
                    unsigned hi, lo;
                    packHL(v0, v1, hi, lo);
                    unsigned wadr = (baseb + (unsigned)(y * 128 + px) * 32) + (oc >> 1);
                    outHi[wadr] = hi;
                    outLo[wadr] = lo;
                }
            }
        }
    }
}

// ---------------- fuse conv: 2-set packed HMMA (R15) -------------------------
__global__ void __launch_bounds__(256) rbmma3_kernel(const float* __restrict__ bias,
                                                     const float* __restrict__ residF,
                                                     float* __restrict__ outF,
                                                     unsigned* __restrict__ outHi,
                                                     unsigned* __restrict__ outLo) {
    extern __shared__ __align__(16) unsigned rsm[];
    unsigned* rowHi = rsm;
    unsigned* rowLo = rsm + 13056;
    unsigned* Bbuf  = rsm + 26112;
    int tid = threadIdx.x;
    int lane = tid & 31, w = tid >> 5;
    int y = blockIdx.x;
    int b = blockIdx.y;
    unsigned baseb = (unsigned)b * HW * 32;

    #pragma unroll
    for (int f = 0; f < 4; ++f) {
        int idx = tid + f * 256;
        cp16(smaddr(Bbuf) + idx * 16, g_wfb + idx * 4, 1);
    }
    cp_commit();

    #pragma unroll
    for (int f = 0; f < 3; ++f) {
        int idx = tid + f * 256;
        int s = idx >> 8;
        int rem = idx & 255;
        int bc = rem >> 5;
        int colc = bc ? (128 + bc) : 0;
        int wadr = (s * 136 + colc) * 32 + (rem & 31);
        rowHi[wadr] = 0u;
        rowLo[wadr] = 0u;
    }
    for (int s = 0; s < 3; ++s) {
        int yy = y + s - 1;
        if ((unsigned)yy < 128u) {
            const unsigned* srcH = g_pUhi + baseb + (unsigned)yy * 128 * 32;
            const unsigned* srcL = g_pUlo + baseb + (unsigned)yy * 128 * 32;
            #pragma unroll
            for (int f = 0; f < 4; ++f) {
                int idx = tid + f * 256;
                int xcol = 1 + (idx >> 3);
                int j4 = (idx & 7) << 2;
                int dstw = (s * 136 + xcol) * 32 + (j4 ^ ((xcol & 7) << 2));
                cp16(smaddr(rowHi) + dstw * 4, srcH + (xcol - 1) * 32 + j4, 1);
                cp16(smaddr(rowLo) + dstw * 4, srcL + (xcol - 1) * 32 + j4, 1);
            }
        } else {
            #pragma unroll
            for (int f = 0; f < 17; ++f) {
                int idx = tid + f * 256;
                int wadr = s * 136 * 32 + idx;
                rowHi[wadr] = 0u;
                rowLo[wadr] = 0u;
            }
        }
    }
    cp_commit();

    int m0 = (w >> 1) * 32;
    int oc0 = (w & 1) * 32;
    int lrow = lane & 7, mi = lane >> 3;
    int jbase0 = m0 + lrow + ((mi & 1) << 3);
    int ocb0 = oc0 + ((mi >> 1) << 3) + lrow;
    unsigned bwordBase[2][2][4];
    #pragma unroll
    for (int np = 0; np < 2; ++np) {
        int oc = ocb0 + np * 16;
        #pragma unroll
        for (int chunk = 0; chunk < 4; ++chunk) {
            int gB = chunk * 2 + (mi & 1);
            unsigned wd = oc * 32 + ((gB ^ (oc & 7)) << 2);
            bwordBase[np][0][chunk] = wd;
            bwordBase[np][1][chunk] = wd + 2048;
        }
    }

    float acc[2][4][4];
    #pragma unroll
    for (int mt = 0; mt < 2; ++mt)
        #pragma unroll
        for (int nt = 0; nt < 4; ++nt)
            #pragma unroll
            for (int e = 0; e < 4; ++e) acc[mt][nt][e] = 0.f;

    unsigned rowHiA = smaddr(rowHi);
    unsigned rowLoA = smaddr(rowLo);

    for (int it = 0; it < 18; ++it) {
        cp_wait<0>();
        __syncthreads();
        if (it == 9) {
            for (int s = 0; s < 3; ++s) {
                int yy = y + s - 1;
                if ((unsigned)yy < 128u) {
                    const unsigned* srcH = g_pVhi + baseb + (unsigned)yy * 128 * 32;
                    const unsigned* srcL = g_pVlo + baseb + (unsigned)yy * 128 * 32;
                    #pragma unroll
                    for (int f = 0; f < 4; ++f) {
                        int idx = tid + f * 256;
                        int xcol = 1 + (idx >> 3);
                        int j4 = (idx & 7) << 2;
                        int dstw = (s * 136 + xcol) * 32 + (j4 ^ ((xcol & 7) << 2));
                        cp16(smaddr(rowHi) + dstw * 4, srcH + (xcol - 1) * 32 + j4, 1);
                        cp16(smaddr(rowLo) + dstw * 4, srcL + (xcol - 1) * 32 + j4, 1);
                    }
                }
            }
            cp_commit();
            cp_wait<0>();
            __syncthreads();
        }
        if (it + 1 < 18) {
            unsigned bs = smaddr(Bbuf + ((it + 1) & 1) * 4096);
            const unsigned* src = g_wfb + (it + 1) * 4096;
            #pragma unroll
            for (int f = 0; f < 4; ++f) {
                int idx = tid + f * 256;
                cp16(bs + idx * 16, src + idx * 4, 1);
            }
            cp_commit();
        }
        unsigned Bb = smaddr(Bbuf) + (it & 1) * 4096 * 4;
        int tap = (it < 9) ? it : (it - 9);
        int slot = tap / 3, dxo = tap - slot * 3;
        int srow = slot * 136;

        #pragma unroll
        for (int chunk = 0; chunk < 4; ++chunk) {
            unsigned aH[2][4], aL[2][4];
            #pragma unroll
            for (int mt = 0; mt < 2; ++mt) {
                int m = jbase0 + mt * 16 + dxo;
                int gA = chunk * 2 + (mi >> 1);
                unsigned wd = (unsigned)((srow + m) * 32 + ((gA ^ (m & 7)) << 2)) * 4u;
                ldsm4(aH[mt], rowHiA + wd);
                ldsm4(aL[mt], rowLoA + wd);
            }
            unsigned bh[2][4], bl[2][4];
            #pragma unroll
            for (int np = 0; np < 2; ++np) {
                ldsm4(bh[np], Bb + bwordBase[np][0][chunk] * 4u);
                ldsm4(bl[np], Bb + bwordBase[np][1][chunk] * 4u);
            }
            #pragma unroll
            for (int np = 0; np < 2; ++np)
                #pragma unroll
                for (int h = 0; h < 2; ++h)
                    #pragma unroll
                    for (int mt = 0; mt < 2; ++mt)
                        mma_bf16(acc[mt][np * 2 + h], aH[mt], bh[np][h * 2], bh[np][h * 2 + 1]);
            #pragma unroll
            for (int np = 0; np < 2; ++np)
                #pragma unroll
                for (int h = 0; h < 2; ++h)
                    #pragma unroll
                    for (int mt = 0; mt < 2; ++mt)
                        mma_bf16(acc[mt][np * 2 + h], aL[mt], bh[np][h * 2], bh[np][h * 2 + 1]);
            #pragma unroll
            for (int np = 0; np < 2; ++np)
                #pragma unroll
                for (int h = 0; h < 2; ++h)
                    #pragma unroll
                    for (int mt = 0; mt < 2; ++mt)
                        mma_bf16(acc[mt][np * 2 + h], aH[mt], bl[np][h * 2], bl[np][h * 2 + 1]);
        }
    }

    int qq = lane & 3;
    int rr = lane >> 2;
    #pragma unroll
    for (int mt = 0; mt < 2; ++mt) {
        #pragma unroll
        for (int nt = 0; nt < 4; ++nt) {
            int px0 = m0 + mt * 16 + rr;
            int oc = oc0 + nt * 8 + 2 * qq;
            float bv0 = bias[oc], bv1 = bias[oc + 1];
            #pragma unroll
            for (int half = 0; half < 2; ++half) {
                int px = px0 + half * 8;
                float v0 = acc[mt][nt][half * 2 + 0] + bv0;
                float v1 = acc[mt][nt][half * 2 + 1] + bv1;
                int oi0 = (b * NF + oc) * HW + y * 128 + px;
                v0 += residF[oi0];
                v1 += residF[oi0 + HW];
                outF[oi0] = v0;
                outF[oi0 + HW] = v1;
                unsigned hi, lo;
                packHL(v0, v1, hi, lo);
                unsigned wadr = (baseb + (unsigned)(y * 128 + px) * 32) + (oc >> 1);
                outHi[wadr] = hi;
                outLo[wadr] = lo;
            }
        }
    }
}

// ---------------- host launcher ----------------------------------------------
extern "C" void kernel_launch(void* const* d_in, const int* in_sizes, int n_in,
                              void* d_out, int out_size) {
    (void)in_sizes; (void)n_in; (void)out_size;
    const float* x      = (const float*)d_in[0];
    const float* T      = (const float*)d_in[1];
    const float* S      = (const float*)d_in[2];
    const float* off_w  = (const float*)d_in[3];
    const float* off_b  = (const float*)d_in[4];
    const float* mod_w  = (const float*)d_in[5];
    const float* mod_b  = (const float*)d_in[6];
    const float* reg_w  = (const float*)d_in[7];
    const float* reg_b  = (const float*)d_in[8];
    const float* fuse_w = (const float*)d_in[9];
    const float* fuse_b = (const float*)d_in[10];
    const float* rb_w1  = (const float*)d_in[11];
    const float* rb_b1  = (const float*)d_in[12];
    const float* rb_w2  = (const float*)d_in[13];
    const float* rb_b2  = (const float*)d_in[14];
    float* out = (float*)d_out;

    const int DEFORM_SMEM = (8192 + 2 * 4096) * 4;
    const int RB2_SMEM    = (2 * 17408 + 8192) * 4;      // 172032 B
    const int RB3_SMEM    = (26112 + 8192) * 4;          // 137216 B
    const int CV2_SMEM    = (26112 + 4096) * 4;          // 120832 B
    cudaFuncSetAttribute(deform_kernel, cudaFuncAttributeMaxDynamicSharedMemorySize, DEFORM_SMEM);
    cudaFuncSetAttribute(rbmma2_kernel, cudaFuncAttributeMaxDynamicSharedMemorySize, RB2_SMEM);
    cudaFuncSetAttribute(rbmma3_kernel, cudaFuncAttributeMaxDynamicSharedMemorySize, RB3_SMEM);
    cudaFuncSetAttribute(convom2_kernel, cudaFuncAttributeMaxDynamicSharedMemorySize, CV2_SMEM);

    float *wreg, *xA;
    unsigned *wbm1, *wbm2, *pXhi, *pXlo, *pThi, *pTlo;
    cudaGetSymbolAddress((void**)&wreg,  g_wreg);
    cudaGetSymbolAddress((void**)&wbm1,  g_wbm1);
    cudaGetSymbolAddress((void**)&wbm2,  g_wbm2);
    cudaGetSymbolAddress((void**)&xA,    g_xA);
    cudaGetSymbolAddress((void**)&pXhi,  g_pXhi);
    cudaGetSymbolAddress((void**)&pXlo,  g_pXlo);
    cudaGetSymbolAddress((void**)&pThi,  g_pThi);
    cudaGetSymbolAddress((void**)&pTlo,  g_pTlo);

    sup_kernel<<<(TOPK * BATCH * HW + 255) / 256, 256>>>(S);
    ref_kernel<<<(TOPK * BATCH * NF * HW / 4 + 255) / 256, 256>>>(T);
    pack_ref<<<(TOPK * BATCH * HW * 32 + 255) / 256, 256>>>();
    {
        int tot = 8 * 9 * 64 * 32;
        wt_wbm<<<(tot + 255) / 256, 256>>>(rb_w1, wbm1);
        wt_wbm<<<(tot + 255) / 256, 256>>>(rb_w2, wbm2);
    }
    {
        int tot = TOPK * 18 * 32 * 32;
        wt_womb<<<(tot + 255) / 256, 256>>>(off_w, mod_w);
    }
    {
        int tot = TOPK * 64 * 9 * 64;
        wt_generic<<<(tot + 255) / 256, 256>>>(reg_w, wreg, 64, 64, 64, tot);
    }
    {
        int tot = 2 * 9 * 64 * 32;
        wt_wfb<<<(tot + 255) / 256, 256>>>(fuse_w);
    }
    pack_x<<<(BATCH * HW * 32 + 255) / 256, 256>>>(x);
    convom2_kernel<<<dim3(128, 12), 256, CV2_SMEM>>>(off_b, mod_b);
    deform_kernel<<<dim3(4, 32, 4), 256, DEFORM_SMEM>>>(reg_b);
    rbmma3_kernel<<<dim3(128, 4), 256, RB3_SMEM>>>(fuse_b, x, xA, pXhi, pXlo);

    for (int r = 0; r < 8; ++r) {
        rbmma2_kernel<<<dim3(64, 4), 512, RB2_SMEM>>>(pXhi, pXlo, wbm1 + r * 36864,
                                                      rb_b1 + r * 64,
                                                      (const float*)0, (float*)0,
                                                      pThi, pTlo, 1);
        float* o = (r == 7) ? out : xA;
        rbmma2_kernel<<<dim3(64, 4), 512, RB2_SMEM>>>(pThi, pTlo, wbm2 + r * 36864,
                                                      rb_b2 + r * 64,
                                                      xA, o,
                                                      (r == 7) ? (unsigned*)0 : pXhi,
                                                      (r == 7) ? (unsigned*)0 : pXlo, 0);
    }
}